// round 1
// baseline (speedup 1.0000x reference)
#include <cuda_runtime.h>
#include <math.h>

#define BB 4096
#define DD 128
#define NN 8192
#define NCHUNK 8
#define TILE 128
#define PAD 129   // smem row pitch (floats); makes strided LDS conflict-free

// Scratch (no allocations allowed in kernel_launch)
__device__ float g_Z[NN * DD];          // normalized rows: [z_i ; z_j]
__device__ float g_part[NCHUNK * NN];   // per-chunk partial row sums of exp
__device__ float g_pos[BB];             // dot(Z_i, Z_{i+B})

// ---------------------------------------------------------------------------
// 1) L2-normalize: one warp per row, float4 loads (D=128 -> 32 float4/row)
// ---------------------------------------------------------------------------
__global__ void k_normalize(const float* __restrict__ zi,
                            const float* __restrict__ zj) {
    int warp = (blockIdx.x * blockDim.x + threadIdx.x) >> 5;
    int lane = threadIdx.x & 31;
    if (warp >= NN) return;
    const float* src = (warp < BB) ? (zi + (size_t)warp * DD)
                                   : (zj + (size_t)(warp - BB) * DD);
    float4 v = ((const float4*)src)[lane];
    float s = v.x * v.x + v.y * v.y + v.z * v.z + v.w * v.w;
    #pragma unroll
    for (int o = 16; o; o >>= 1) s += __shfl_xor_sync(0xffffffffu, s, o);
    float inv = 1.0f / fmaxf(sqrtf(s), 1e-12f);
    float4 o4 = make_float4(v.x * inv, v.y * inv, v.z * inv, v.w * inv);
    ((float4*)(g_Z + (size_t)warp * DD))[lane] = o4;
}

// ---------------------------------------------------------------------------
// 2) Positive-pair dots: dot(Z_i, Z_{i+B}), one warp per pair
// ---------------------------------------------------------------------------
__global__ void k_pos() {
    int warp = (blockIdx.x * blockDim.x + threadIdx.x) >> 5;
    int lane = threadIdx.x & 31;
    if (warp >= BB) return;
    float4 va = ((const float4*)(g_Z + (size_t)warp * DD))[lane];
    float4 vb = ((const float4*)(g_Z + (size_t)(warp + BB) * DD))[lane];
    float s = va.x * vb.x + va.y * vb.y + va.z * vb.z + va.w * vb.w;
    #pragma unroll
    for (int o = 16; o; o >>= 1) s += __shfl_xor_sync(0xffffffffu, s, o);
    if (lane == 0) g_pos[warp] = s;
}

// ---------------------------------------------------------------------------
// 3) Fused Gram + exp + row-sum.
//    Block = 256 threads (16x16), each thread owns an 8x8 microtile.
//    grid = (NCHUNK=8 column chunks, 64 row tiles). Each block:
//      - loads its 128-row A tile once,
//      - streams 8 column tiles of 128 rows,
//      - epilogue: acc_row += exp(2*c) with diagonal skipped,
//      - writes per-chunk row partials (deterministic, no atomics).
// ---------------------------------------------------------------------------
__global__ void __launch_bounds__(256) k_sim() {
    extern __shared__ float sm[];
    float* As = sm;                 // TILE*PAD floats
    float* Bs = sm + TILE * PAD;    // TILE*PAD floats

    int tid = threadIdx.x;
    int tx = tid & 15;              // column group
    int ty = tid >> 4;              // row group
    int rowTile = blockIdx.y * TILE;
    int chunk = blockIdx.x;

    // Load A tile (rows rowTile..rowTile+127), row-major with pitch PAD
    #pragma unroll
    for (int i = 0; i < 16; i++) {
        int idx = tid + 256 * i;        // float4 index within 128x32 tile
        int m = idx >> 5;
        int c4 = idx & 31;
        float4 v = ((const float4*)(g_Z + (size_t)(rowTile + m) * DD))[c4];
        float* p = As + m * PAD + c4 * 4;
        p[0] = v.x; p[1] = v.y; p[2] = v.z; p[3] = v.w;
    }

    float acc[8];
    #pragma unroll
    for (int i = 0; i < 8; i++) acc[i] = 0.f;

    for (int t = 0; t < 8; t++) {
        int colTile = chunk * (NCHUNK * TILE) + t * TILE;
        __syncthreads();  // A ready (t=0) / previous Bs fully consumed
        #pragma unroll
        for (int i = 0; i < 16; i++) {
            int idx = tid + 256 * i;
            int n = idx >> 5;
            int c4 = idx & 31;
            float4 v = ((const float4*)(g_Z + (size_t)(colTile + n) * DD))[c4];
            float* p = Bs + n * PAD + c4 * 4;
            p[0] = v.x; p[1] = v.y; p[2] = v.z; p[3] = v.w;
        }
        __syncthreads();

        float c[8][8];
        #pragma unroll
        for (int i = 0; i < 8; i++)
            #pragma unroll
            for (int j = 0; j < 8; j++) c[i][j] = 0.f;

        #pragma unroll 8
        for (int k = 0; k < DD; k++) {
            float a[8], b[8];
            #pragma unroll
            for (int i = 0; i < 8; i++) a[i] = As[(ty * 8 + i) * PAD + k];
            #pragma unroll
            for (int j = 0; j < 8; j++) b[j] = Bs[(tx + 16 * j) * PAD + k];
            #pragma unroll
            for (int i = 0; i < 8; i++)
                #pragma unroll
                for (int j = 0; j < 8; j++) c[i][j] = fmaf(a[i], b[j], c[i][j]);
        }

        // Epilogue: exp(logit) with diagonal masked, accumulate per-row
        #pragma unroll
        for (int i = 0; i < 8; i++) {
            int gr = rowTile + ty * 8 + i;
            float s = 0.f;
            #pragma unroll
            for (int j = 0; j < 8; j++) {
                int gc = colTile + tx + 16 * j;
                float e = __expf(2.0f * c[i][j]);   // 1/TEMPERATURE = 2
                s += (gr == gc) ? 0.f : e;
            }
            acc[i] += s;
        }
    }

    // Reduce the 16 tx-partials per row (reuse As as 128x16 scratch)
    __syncthreads();
    #pragma unroll
    for (int i = 0; i < 8; i++) As[(ty * 8 + i) * 16 + tx] = acc[i];
    __syncthreads();
    if (tid < TILE) {
        float s = 0.f;
        #pragma unroll
        for (int j = 0; j < 16; j++) s += As[tid * 16 + j];
        g_part[chunk * NN + rowTile + tid] = s;
    }
}

// ---------------------------------------------------------------------------
// 4) Final reduction: loss = (sum_r log(rowsum_r) - 4*sum_i posdot_i) / N
//    (sum of positive logits over all 2B rows = 2 * sum_i 2*dot_i)
//    Single block, fixed-order -> deterministic.
// ---------------------------------------------------------------------------
__global__ void k_final(float* __restrict__ out) {
    __shared__ float sred[1024];
    int tid = threadIdx.x;
    float s = 0.f;
    for (int r = tid; r < NN; r += 1024) {
        float rs = 0.f;
        #pragma unroll
        for (int c = 0; c < NCHUNK; c++) rs += g_part[c * NN + r];
        s += logf(rs);
    }
    for (int i = tid; i < BB; i += 1024) s -= 4.0f * g_pos[i];
    sred[tid] = s;
    __syncthreads();
    for (int o = 512; o; o >>= 1) {
        if (tid < o) sred[tid] += sred[tid + o];
        __syncthreads();
    }
    if (tid == 0) out[0] = sred[0] / (float)NN;
}

// ---------------------------------------------------------------------------
extern "C" void kernel_launch(void* const* d_in, const int* in_sizes, int n_in,
                              void* d_out, int out_size) {
    (void)in_sizes; (void)n_in; (void)out_size;
    const float* zi = (const float*)d_in[0];
    const float* zj = (const float*)d_in[1];
    float* out = (float*)d_out;

    size_t smem = (size_t)2 * TILE * PAD * sizeof(float);  // 132 KB
    cudaFuncSetAttribute(k_sim, cudaFuncAttributeMaxDynamicSharedMemorySize,
                         (int)smem);

    k_normalize<<<NN / 8, 256>>>(zi, zj);
    k_pos<<<BB / 8, 256>>>();
    k_sim<<<dim3(NCHUNK, NN / TILE), 256, smem>>>();
    k_final<<<1, 1024>>>(out);
}

// round 3
// speedup vs baseline: 7.9807x; 7.9807x over previous
#include <cuda_runtime.h>
#include <cuda_bf16.h>
#include <math.h>
#include <stdint.h>

#define BB 4096
#define DD 128
#define NN 8192
#define NCHUNK 2                  // column chunks (grid.x)
#define NT (NN / NCHUNK / 128)    // 32 col tiles of 128 per chunk
#define NCH2 (NCHUNK * 2)         // partial slots (2 warp-cols per CTA)
#define EXS 2.885390082f          // 2 * log2(e)  (1/T = 2)

// ---------------- device scratch ----------------
__device__ __align__(16) float          g_Z[NN * DD];
__device__ __align__(16) __nv_bfloat16  g_Zh[NN * DD];
__device__ float g_part[NCH2 * NN];
__device__ float g_pos[BB];
__device__ float g_red[64];

// ---------------- helpers ----------------
__device__ __forceinline__ uint32_t smem_u32(const void* p) {
    uint32_t a;
    asm("{ .reg .u64 t; cvta.to.shared.u64 t, %1; cvt.u32.u64 %0, t; }"
        : "=r"(a) : "l"(p));
    return a;
}
__device__ __forceinline__ float ex2(float x) {
    float y;
    asm("ex2.approx.ftz.f32 %0, %1;" : "=f"(y) : "f"(x));
    return y;
}
__device__ __forceinline__ void ldsm4(uint32_t (&r)[4], uint32_t addr) {
    asm volatile("ldmatrix.sync.aligned.m8n8.x4.shared.b16 {%0,%1,%2,%3}, [%4];"
                 : "=r"(r[0]), "=r"(r[1]), "=r"(r[2]), "=r"(r[3]) : "r"(addr));
}
__device__ __forceinline__ void mma16816(float (&d)[4], const uint32_t (&a)[4],
                                         uint32_t b0, uint32_t b1) {
    asm volatile("mma.sync.aligned.m16n8k16.row.col.f32.bf16.bf16.f32 "
                 "{%0,%1,%2,%3},{%4,%5,%6,%7},{%8,%9},{%0,%1,%2,%3};"
                 : "+f"(d[0]), "+f"(d[1]), "+f"(d[2]), "+f"(d[3])
                 : "r"(a[0]), "r"(a[1]), "r"(a[2]), "r"(a[3]), "r"(b0), "r"(b1));
}

// ---------------------------------------------------------------------------
// 1) L2-normalize (one warp/row) -> fp32 + bf16 copies
// ---------------------------------------------------------------------------
__global__ void k_normalize(const float* __restrict__ zi,
                            const float* __restrict__ zj) {
    int warp = (blockIdx.x * blockDim.x + threadIdx.x) >> 5;
    int lane = threadIdx.x & 31;
    if (warp >= NN) return;
    const float* src = (warp < BB) ? (zi + (size_t)warp * DD)
                                   : (zj + (size_t)(warp - BB) * DD);
    float4 v = ((const float4*)src)[lane];
    float s = v.x * v.x + v.y * v.y + v.z * v.z + v.w * v.w;
    #pragma unroll
    for (int o = 16; o; o >>= 1) s += __shfl_xor_sync(0xffffffffu, s, o);
    float inv = 1.0f / fmaxf(sqrtf(s), 1e-12f);
    float4 o4 = make_float4(v.x * inv, v.y * inv, v.z * inv, v.w * inv);
    ((float4*)(g_Z + (size_t)warp * DD))[lane] = o4;
    __nv_bfloat162* dst = (__nv_bfloat162*)(g_Zh + (size_t)warp * DD);
    dst[lane * 2]     = __floats2bfloat162_rn(o4.x, o4.y);
    dst[lane * 2 + 1] = __floats2bfloat162_rn(o4.z, o4.w);
}

// ---------------------------------------------------------------------------
// 2) Positive-pair dots (exact fp32)
// ---------------------------------------------------------------------------
__global__ void k_pos() {
    int warp = (blockIdx.x * blockDim.x + threadIdx.x) >> 5;
    int lane = threadIdx.x & 31;
    if (warp >= BB) return;
    float4 va = ((const float4*)(g_Z + (size_t)warp * DD))[lane];
    float4 vb = ((const float4*)(g_Z + (size_t)(warp + BB) * DD))[lane];
    float s = va.x * vb.x + va.y * vb.y + va.z * vb.z + va.w * vb.w;
    #pragma unroll
    for (int o = 16; o; o >>= 1) s += __shfl_xor_sync(0xffffffffu, s, o);
    if (lane == 0) g_pos[warp] = s;
}

// ---------------------------------------------------------------------------
// Tile movement: 128x128 bf16 tiles, 16B chunks, xor-swizzle (c4 ^ (row&7))
// ---------------------------------------------------------------------------
__device__ __forceinline__ void ldg_tile(uint4 (&p)[8], int rowBase, int tid) {
    const uint4* gz = (const uint4*)g_Zh;      // 16 uint4 per row
    #pragma unroll
    for (int i = 0; i < 8; i++) {
        int idx = tid + 256 * i;
        int r = idx >> 4, c4 = idx & 15;
        p[i] = gz[(size_t)(rowBase + r) * 16 + c4];
    }
}
__device__ __forceinline__ void sts_tile(char* base, const uint4 (&p)[8], int tid) {
    #pragma unroll
    for (int i = 0; i < 8; i++) {
        int idx = tid + 256 * i;
        int r = idx >> 4, c4 = idx & 15;
        *(uint4*)(base + r * 256 + ((c4 ^ (r & 7)) << 4)) = p[i];
    }
}

// ---------------------------------------------------------------------------
// 3) HMMA Gram + fused exp/row-sum.
//    256 thr = 8 warps (4 Mx2 N). CTA tile 128 rows; streams NT col tiles.
//    Warp tile 32x64: 2 m16 x 8 n8 frags, K=128 in 8 k-steps.
// ---------------------------------------------------------------------------
__global__ void __launch_bounds__(256, 1) k_sim() {
    extern __shared__ char dyn[];
    char* sm0 = (char*)(((uintptr_t)dyn + 1023) & ~(uintptr_t)1023);
    char* As  = sm0;                 // 32 KB
    char* Bs0 = sm0 + 32768;         // 32 KB
    char* Bs1 = sm0 + 65536;         // 32 KB
    uint32_t suA  = smem_u32(As);
    uint32_t suB0 = smem_u32(Bs0);
    uint32_t suB1 = smem_u32(Bs1);

    int tid = threadIdx.x;
    int wid = tid >> 5, lane = tid & 31;
    int chunk = blockIdx.x;
    int rowTile = blockIdx.y * 128;
    int colBase = chunk * (NT * 128);

    int warpM = (wid >> 1) * 32;
    int warpN = (wid & 1) * 64;

    // ldmatrix lane geometry
    int subA = lane >> 3;
    int rowoffA = (lane & 7) + 8 * (subA & 1);
    int cpartA = subA >> 1;
    int subB = lane >> 3;
    int noffB = (lane & 7) + 8 * (subB >> 1);
    int cpartB = subB & 1;
    int xm = lane & 7;

    uint32_t aAddr0 = suA + (uint32_t)(warpM + rowoffA) * 256u;
    uint32_t aAddr1 = aAddr0 + 16u * 256u;
    uint32_t bOff[4];
    #pragma unroll
    for (int ng = 0; ng < 4; ng++)
        bOff[ng] = (uint32_t)(warpN + ng * 16 + noffB) * 256u;

    // prologue: A tile + first B tile
    uint4 pa[8], pb[8];
    ldg_tile(pa, rowTile, tid);
    ldg_tile(pb, colBase, tid);
    sts_tile(As, pa, tid);
    sts_tile(Bs0, pb, tid);

    float accRow[2][2] = {{0.f, 0.f}, {0.f, 0.f}};   // [mt][half]

    for (int t = 0; t < NT; t++) {
        __syncthreads();                       // B tile t ready; other buf free
        int colTile = colBase + t * 128;
        uint32_t bufB = (t & 1) ? suB1 : suB0;

        if (t + 1 < NT) ldg_tile(pb, colTile + 128, tid);

        float acc[2][8][4];
        #pragma unroll
        for (int mt = 0; mt < 2; mt++)
            #pragma unroll
            for (int nt = 0; nt < 8; nt++)
                #pragma unroll
                for (int e = 0; e < 4; e++) acc[mt][nt][e] = 0.f;

        #pragma unroll
        for (int kk = 0; kk < 8; kk++) {
            uint32_t ca = (uint32_t)(((2 * kk + cpartA) ^ xm) << 4);
            uint32_t cb = (uint32_t)(((2 * kk + cpartB) ^ xm) << 4);
            uint32_t a0[4], a1[4];
            ldsm4(a0, aAddr0 + ca);
            ldsm4(a1, aAddr1 + ca);
            #pragma unroll
            for (int ng = 0; ng < 4; ng++) {
                uint32_t b[4];
                ldsm4(b, bufB + bOff[ng] + cb);
                mma16816(acc[0][2 * ng],     a0, b[0], b[1]);
                mma16816(acc[0][2 * ng + 1], a0, b[2], b[3]);
                mma16816(acc[1][2 * ng],     a1, b[0], b[1]);
                mma16816(acc[1][2 * ng + 1], a1, b[2], b[3]);
            }
        }

        // fused epilogue: exp(2*logit) row-sums
        if (colTile != rowTile) {
            #pragma unroll
            for (int mt = 0; mt < 2; mt++) {
                float s0 = 0.f, s1 = 0.f;
                #pragma unroll
                for (int nt = 0; nt < 8; nt++) {
                    s0 += ex2(acc[mt][nt][0] * EXS) + ex2(acc[mt][nt][1] * EXS);
                    s1 += ex2(acc[mt][nt][2] * EXS) + ex2(acc[mt][nt][3] * EXS);
                }
                accRow[mt][0] += s0;
                accRow[mt][1] += s1;
            }
        } else {
            // diagonal tile: zero the logit at global row == global col
            #pragma unroll
            for (int mt = 0; mt < 2; mt++) {
                int r0 = warpM + mt * 16 + (lane >> 2);  // local row (== local col space)
                float s0 = 0.f, s1 = 0.f;
                #pragma unroll
                for (int nt = 0; nt < 8; nt++) {
                    int c0 = warpN + nt * 8 + (lane & 3) * 2;
                    float e0 = ex2(acc[mt][nt][0] * EXS);
                    float e1 = ex2(acc[mt][nt][1] * EXS);
                    float e2 = ex2(acc[mt][nt][2] * EXS);
                    float e3 = ex2(acc[mt][nt][3] * EXS);
                    s0 += (r0 == c0     ? 0.f : e0) + (r0 == c0 + 1     ? 0.f : e1);
                    s1 += (r0 + 8 == c0 ? 0.f : e2) + (r0 + 8 == c0 + 1 ? 0.f : e3);
                }
                accRow[mt][0] += s0;
                accRow[mt][1] += s1;
            }
        }

        if (t + 1 < NT) sts_tile((t & 1) ? Bs0 : Bs1, pb, tid);
    }

    // reduce quads (lanes covering distinct cols of the same row)
    #pragma unroll
    for (int mt = 0; mt < 2; mt++)
        #pragma unroll
        for (int h = 0; h < 2; h++) {
            float v = accRow[mt][h];
            v += __shfl_xor_sync(0xffffffffu, v, 1);
            v += __shfl_xor_sync(0xffffffffu, v, 2);
            if ((lane & 3) == 0) {
                int row = rowTile + warpM + mt * 16 + 8 * h + (lane >> 2);
                g_part[(chunk * 2 + (wid & 1)) * NN + row] = v;
            }
        }
}

// ---------------------------------------------------------------------------
// 4) Final reduction (two tiny deterministic stages)
// ---------------------------------------------------------------------------
__global__ void k_final1() {
    __shared__ float sred[128];
    int tid = threadIdx.x;
    int row = blockIdx.x * 128 + tid;
    float rs = 0.f;
    #pragma unroll
    for (int c = 0; c < NCH2; c++) rs += g_part[c * NN + row];
    float v = logf(rs) - 2.0f * g_pos[row & (BB - 1)];
    sred[tid] = v;
    __syncthreads();
    #pragma unroll
    for (int o = 64; o; o >>= 1) {
        if (tid < o) sred[tid] += sred[tid + o];
        __syncthreads();
    }
    if (tid == 0) g_red[blockIdx.x] = sred[0];
}
__global__ void k_final2(float* __restrict__ out) {
    __shared__ float s[64];
    int tid = threadIdx.x;
    s[tid] = g_red[tid];
    __syncthreads();
    #pragma unroll
    for (int o = 32; o; o >>= 1) {
        if (tid < o) s[tid] += s[tid + o];
        __syncthreads();
    }
    if (tid == 0) out[0] = s[0] / (float)NN;
}

// ---------------------------------------------------------------------------
extern "C" void kernel_launch(void* const* d_in, const int* in_sizes, int n_in,
                              void* d_out, int out_size) {
    (void)in_sizes; (void)n_in; (void)out_size;
    const float* zi = (const float*)d_in[0];
    const float* zj = (const float*)d_in[1];
    float* out = (float*)d_out;

    size_t smem = 1024 + 3 * 32768;   // align pad + A + 2x B
    cudaFuncSetAttribute(k_sim, cudaFuncAttributeMaxDynamicSharedMemorySize,
                         (int)smem);

    k_normalize<<<NN / 8, 256>>>(zi, zj);
    k_pos<<<BB / 8, 256>>>();
    k_sim<<<dim3(NCHUNK, NN / 128), 256, smem>>>();
    k_final1<<<64, 128>>>();
    k_final2<<<1, 64>>>(out);
}

// round 4
// speedup vs baseline: 10.6828x; 1.3386x over previous
#include <cuda_runtime.h>
#include <cuda_bf16.h>
#include <math.h>
#include <stdint.h>

#define BB 4096
#define DD 128
#define NN 8192
#define NBLK 64                   // 128-row blocks
#define NTILES 2080               // NBLK*(NBLK+1)/2 upper-triangular tiles
#define GRID_SIM 148
#define EXS 2.885390082f          // 2 * log2(e)  (1/T = 2)

// ---------------- device scratch ----------------
__device__ __align__(16) float          g_Z[NN * DD];
__device__ __align__(16) __nv_bfloat16  g_Zh[NN * DD];
__device__ float g_part[NBLK * NN];   // slot s, row r: unique single writer
__device__ float g_red[64];

// ---------------- helpers ----------------
__device__ __forceinline__ uint32_t smem_u32(const void* p) {
    uint32_t a;
    asm("{ .reg .u64 t; cvta.to.shared.u64 t, %1; cvt.u32.u64 %0, t; }"
        : "=r"(a) : "l"(p));
    return a;
}
__device__ __forceinline__ float ex2(float x) {
    float y;
    asm("ex2.approx.ftz.f32 %0, %1;" : "=f"(y) : "f"(x));
    return y;
}
__device__ __forceinline__ void ldsm4(uint32_t (&r)[4], uint32_t addr) {
    asm volatile("ldmatrix.sync.aligned.m8n8.x4.shared.b16 {%0,%1,%2,%3}, [%4];"
                 : "=r"(r[0]), "=r"(r[1]), "=r"(r[2]), "=r"(r[3]) : "r"(addr));
}
__device__ __forceinline__ void mma16816(float (&d)[4], const uint32_t (&a)[4],
                                         uint32_t b0, uint32_t b1) {
    asm volatile("mma.sync.aligned.m16n8k16.row.col.f32.bf16.bf16.f32 "
                 "{%0,%1,%2,%3},{%4,%5,%6,%7},{%8,%9},{%0,%1,%2,%3};"
                 : "+f"(d[0]), "+f"(d[1]), "+f"(d[2]), "+f"(d[3])
                 : "r"(a[0]), "r"(a[1]), "r"(a[2]), "r"(a[3]), "r"(b0), "r"(b1));
}
__device__ __forceinline__ void cp16(uint32_t s, const void* g) {
    asm volatile("cp.async.cg.shared.global [%0], [%1], 16;" :: "r"(s), "l"(g));
}
#define CP_COMMIT() asm volatile("cp.async.commit_group;" ::: "memory")
#define CP_WAIT(n)  asm volatile("cp.async.wait_group %0;" :: "n"(n) : "memory")

// idx -> (rt, ct), ct >= rt, row-major over the upper triangle
__device__ __forceinline__ void tile_map(int idx, int& rt, int& ct) {
    float f = 129.0f * 129.0f - 8.0f * (float)idx;
    int r = (int)((129.0f - sqrtf(f)) * 0.5f);
    if (r > 63) r = 63;
    if (r < 0) r = 0;
    while (r * (129 - r) / 2 > idx) --r;
    while ((r + 1) * (128 - r) / 2 <= idx) ++r;
    rt = r;
    ct = r + (idx - r * (129 - r) / 2);
}

// ---------------------------------------------------------------------------
// 1) L2-normalize (one warp/row) -> fp32 + bf16 copies
// ---------------------------------------------------------------------------
__global__ void k_normalize(const float* __restrict__ zi,
                            const float* __restrict__ zj) {
    int warp = (blockIdx.x * blockDim.x + threadIdx.x) >> 5;
    int lane = threadIdx.x & 31;
    if (warp >= NN) return;
    const float* src = (warp < BB) ? (zi + (size_t)warp * DD)
                                   : (zj + (size_t)(warp - BB) * DD);
    float4 v = ((const float4*)src)[lane];
    float s = v.x * v.x + v.y * v.y + v.z * v.z + v.w * v.w;
    #pragma unroll
    for (int o = 16; o; o >>= 1) s += __shfl_xor_sync(0xffffffffu, s, o);
    float inv = 1.0f / fmaxf(sqrtf(s), 1e-12f);
    float4 o4 = make_float4(v.x * inv, v.y * inv, v.z * inv, v.w * inv);
    ((float4*)(g_Z + (size_t)warp * DD))[lane] = o4;
    __nv_bfloat162* dst = (__nv_bfloat162*)(g_Zh + (size_t)warp * DD);
    dst[lane * 2]     = __floats2bfloat162_rn(o4.x, o4.y);
    dst[lane * 2 + 1] = __floats2bfloat162_rn(o4.z, o4.w);
}

// ---------------------------------------------------------------------------
// cp.async a 128x128 bf16 block into a swizzled smem tile (all 256 threads)
// ---------------------------------------------------------------------------
__device__ __forceinline__ void cpa_tile(uint32_t sbase, int rowBase, int tid) {
    const char* g = (const char*)g_Zh + (size_t)rowBase * 256;
    #pragma unroll
    for (int i = 0; i < 8; i++) {
        int idx = tid + 256 * i;
        int r = idx >> 4, c4 = idx & 15;
        cp16(sbase + (uint32_t)(r * 256 + ((c4 ^ (r & 7)) << 4)),
             g + r * 256 + c4 * 16);
    }
}

// ---------------------------------------------------------------------------
// 2) Triangular HMMA Gram + fused exp / row+col sums.
//    148 persistent CTAs stride the 2080-tile list. Double-buffered cp.async.
// ---------------------------------------------------------------------------
__global__ void __launch_bounds__(256, 1) k_sim() {
    extern __shared__ char dyn[];
    __shared__ float sRow[2][128];
    __shared__ float sCol[4][128];

    char* sm0 = (char*)(((uintptr_t)dyn + 1023) & ~(uintptr_t)1023);
    // buffers: [buf][A|B] each 32 KB
    uint32_t su = smem_u32(sm0);

    int tid = threadIdx.x;
    int wid = tid >> 5, lane = tid & 31;
    int warpM = (wid >> 1) * 32;
    int warpN = (wid & 1) * 64;

    // ldmatrix lane geometry (identical to validated R3 core)
    int subA = lane >> 3;
    int rowoffA = (lane & 7) + 8 * (subA & 1);
    int cpartA = subA >> 1;
    int noffB = (lane & 7) + 8 * (subA >> 1);
    int cpartB = subA & 1;
    int xm = lane & 7;

    int idx = blockIdx.x;
    int rt, ct;
    tile_map(idx, rt, ct);
    cpa_tile(su, rt * 128, tid);           // buf0 A
    cpa_tile(su + 32768, ct * 128, tid);   // buf0 B
    CP_COMMIT();

    for (int i = 0; idx < NTILES; idx += GRID_SIM, ++i) {
        int bi = i & 1;
        uint32_t bufA = su + (uint32_t)bi * 65536u;
        uint32_t bufB = bufA + 32768u;

        int nrt = 0, nct = 0;
        int nidx = idx + GRID_SIM;
        if (nidx < NTILES) {
            tile_map(nidx, nrt, nct);
            uint32_t nb = su + (uint32_t)(bi ^ 1) * 65536u;
            cpa_tile(nb, nrt * 128, tid);
            cpa_tile(nb + 32768, nct * 128, tid);
            CP_COMMIT();
            CP_WAIT(1);
        } else {
            CP_WAIT(0);
        }
        __syncthreads();   // tile ready; prev iter's smem reads done

        uint32_t aAddr0 = bufA + (uint32_t)(warpM + rowoffA) * 256u;
        uint32_t aAddr1 = aAddr0 + 16u * 256u;

        float acc[2][8][4];
        #pragma unroll
        for (int mt = 0; mt < 2; mt++)
            #pragma unroll
            for (int nt = 0; nt < 8; nt++)
                #pragma unroll
                for (int e = 0; e < 4; e++) acc[mt][nt][e] = 0.f;

        #pragma unroll
        for (int kk = 0; kk < 8; kk++) {
            uint32_t ca = (uint32_t)(((2 * kk + cpartA) ^ xm) << 4);
            uint32_t cb = (uint32_t)(((2 * kk + cpartB) ^ xm) << 4);
            uint32_t a0[4], a1[4];
            ldsm4(a0, aAddr0 + ca);
            ldsm4(a1, aAddr1 + ca);
            #pragma unroll
            for (int ng = 0; ng < 4; ng++) {
                uint32_t b[4];
                ldsm4(b, bufB + (uint32_t)(warpN + ng * 16 + noffB) * 256u + cb);
                mma16816(acc[0][2 * ng],     a0, b[0], b[1]);
                mma16816(acc[0][2 * ng + 1], a0, b[2], b[3]);
                mma16816(acc[1][2 * ng],     a1, b[0], b[1]);
                mma16816(acc[1][2 * ng + 1], a1, b[2], b[3]);
            }
        }

        // ---- fused epilogue ----
        float rowp[2][2] = {{0.f, 0.f}, {0.f, 0.f}};
        if (rt != ct) {
            float colp[16];
            #pragma unroll
            for (int q = 0; q < 16; q++) colp[q] = 0.f;
            #pragma unroll
            for (int nt = 0; nt < 8; nt++) {
                #pragma unroll
                for (int mt = 0; mt < 2; mt++) {
                    float e0 = ex2(acc[mt][nt][0] * EXS);
                    float e1 = ex2(acc[mt][nt][1] * EXS);
                    float e2 = ex2(acc[mt][nt][2] * EXS);
                    float e3 = ex2(acc[mt][nt][3] * EXS);
                    rowp[mt][0] += e0 + e1;
                    rowp[mt][1] += e2 + e3;
                    colp[nt * 2]     += e0 + e2;
                    colp[nt * 2 + 1] += e1 + e3;
                }
            }
            // column totals: combine the 8 lanes (stride 4) sharing each column
            #pragma unroll
            for (int q = 0; q < 16; q++) {
                float v = colp[q];
                v += __shfl_xor_sync(0xffffffffu, v, 4);
                v += __shfl_xor_sync(0xffffffffu, v, 8);
                v += __shfl_xor_sync(0xffffffffu, v, 16);
                colp[q] = v;
            }
            if (lane < 4) {
                #pragma unroll
                for (int q = 0; q < 16; q++)
                    sCol[wid >> 1][warpN + (q >> 1) * 8 + lane * 2 + (q & 1)] = colp[q];
            }
        } else {
            // diagonal tile: full row sums with the diagonal element zeroed
            #pragma unroll
            for (int mt = 0; mt < 2; mt++) {
                int r0 = warpM + mt * 16 + (lane >> 2);
                #pragma unroll
                for (int nt = 0; nt < 8; nt++) {
                    int c0 = warpN + nt * 8 + (lane & 3) * 2;
                    float e0 = ex2(acc[mt][nt][0] * EXS);
                    float e1 = ex2(acc[mt][nt][1] * EXS);
                    float e2 = ex2(acc[mt][nt][2] * EXS);
                    float e3 = ex2(acc[mt][nt][3] * EXS);
                    rowp[mt][0] += (r0 == c0     ? 0.f : e0) + (r0 == c0 + 1     ? 0.f : e1);
                    rowp[mt][1] += (r0 + 8 == c0 ? 0.f : e2) + (r0 + 8 == c0 + 1 ? 0.f : e3);
                }
            }
        }
        // row totals: combine the 4 lanes (stride 1) sharing each row
        #pragma unroll
        for (int mt = 0; mt < 2; mt++)
            #pragma unroll
            for (int h = 0; h < 2; h++) {
                float v = rowp[mt][h];
                v += __shfl_xor_sync(0xffffffffu, v, 1);
                v += __shfl_xor_sync(0xffffffffu, v, 2);
                if ((lane & 3) == 0)
                    sRow[wid & 1][warpM + mt * 16 + 8 * h + (lane >> 2)] = v;
            }
        __syncthreads();

        if (tid < 128) {
            float rv = sRow[0][tid] + sRow[1][tid];
            g_part[(size_t)ct * NN + rt * 128 + tid] = rv;       // row sums
            if (rt != ct) {
                float cv = sCol[0][tid] + sCol[1][tid] + sCol[2][tid] + sCol[3][tid];
                g_part[(size_t)rt * NN + ct * 128 + tid] = cv;   // symmetric cols
            }
        }
        rt = nrt; ct = nct;
    }
}

// ---------------------------------------------------------------------------
// 3) Final reduction: rowsum over 64 slots, pos dot inline, log, tree-reduce
// ---------------------------------------------------------------------------
__global__ void k_final1() {
    __shared__ float sred[128];
    int tid = threadIdx.x;
    int row = blockIdx.x * 128 + tid;
    float rs = 0.f;
    #pragma unroll
    for (int s = 0; s < NBLK; s++) rs += g_part[(size_t)s * NN + row];
    // positive logit: 2 * dot(Z[row], Z[row ^ BB]) in exact fp32
    const float4* a = (const float4*)(g_Z + (size_t)row * DD);
    const float4* b = (const float4*)(g_Z + (size_t)(row ^ BB) * DD);
    float dot = 0.f;
    #pragma unroll
    for (int j = 0; j < 32; j++) {
        float4 va = a[j], vb = b[j];
        dot += va.x * vb.x + va.y * vb.y + va.z * vb.z + va.w * vb.w;
    }
    sred[tid] = logf(rs) - 2.0f * dot;
    __syncthreads();
    #pragma unroll
    for (int o = 64; o; o >>= 1) {
        if (tid < o) sred[tid] += sred[tid + o];
        __syncthreads();
    }
    if (tid == 0) g_red[blockIdx.x] = sred[0];
}
__global__ void k_final2(float* __restrict__ out) {
    __shared__ float s[64];
    int tid = threadIdx.x;
    s[tid] = g_red[tid];
    __syncthreads();
    #pragma unroll
    for (int o = 32; o; o >>= 1) {
        if (tid < o) s[tid] += s[tid + o];
        __syncthreads();
    }
    if (tid == 0) out[0] = s[0] / (float)NN;
}

// ---------------------------------------------------------------------------
extern "C" void kernel_launch(void* const* d_in, const int* in_sizes, int n_in,
                              void* d_out, int out_size) {
    (void)in_sizes; (void)n_in; (void)out_size;
    const float* zi = (const float*)d_in[0];
    const float* zj = (const float*)d_in[1];
    float* out = (float*)d_out;

    size_t smem = 1024 + 2 * 65536;   // align pad + 2 x (A 32KB + B 32KB)
    cudaFuncSetAttribute(k_sim, cudaFuncAttributeMaxDynamicSharedMemorySize,
                         (int)smem);

    k_normalize<<<NN / 8, 256>>>(zi, zj);
    k_sim<<<GRID_SIM, 256, smem>>>();
    k_final1<<<64, 128>>>();
    k_final2<<<1, 64>>>(out);
}